// round 12
// baseline (speedup 1.0000x reference)
#include <cuda_runtime.h>
#include <math.h>

#define C 96
#define FOURC 384
#define NN 4096
#define TILE 32
#define NTH 384
#define NCTAS (NN / TILE)   // 128

typedef unsigned long long ull;

#define XS 97               // padded stride for X0/X1/Q/F
#define GS 388              // nf tile rows (16B aligned for cp.async)
#define TS 385              // tp_w rows (odd -> conflict-free scalar)
#define HS 17               // H1/H2 row stride
#define PS 5                // POT row stride
#define X1P (TILE * XS)

// ---------------- shared memory layout (floats) ----------------
#define OFF_B    0          // 9216 : weight buffer A
#define OFF_B2   9216       // 9216 : weight buffer B
#define OFF_X0   18432      // 3104
#define OFF_X1   21536      // 9312
#define OFF_Q    30848      // 3104
#define OFF_F    33952      // 3104
#define OFF_G    37056      // 12416 : nf tile (388), then G2 (96x96), then tp_w (385)
#define OFF_H1   49472      // 544
#define OFF_H2   50016      // 544
#define OFF_POT  50560      // 160
#define SMEM_FLOATS 50720
#define SMEM_BYTES (SMEM_FLOATS * 4)   // 202880 B -> 1 CTA/SM, 12 warps

// ---------------- device scratch ----------------
__device__ __align__(16) float g_G0[C * C];
__device__ __align__(16) float g_G1[C * C];
__device__ __align__(16) float g_G2[C * C];

// ---------------- f32x2 helpers ----------------
__device__ __forceinline__ ull dup2(float a) {
    ull r;
    asm("mov.b64 %0, {%1, %1};" : "=l"(r) : "f"(a));
    return r;
}
__device__ __forceinline__ float2 unp2(ull v) {
    float2 r;
    asm("mov.b64 {%0, %1}, %2;" : "=f"(r.x), "=f"(r.y) : "l"(v));
    return r;
}
#define FMA2(d, a, b, cc) asm("fma.rn.f32x2 %0, %1, %2, %3;" : "=l"(d) : "l"(a), "l"(b), "l"(cc))

// NS activation streams x 8 cols vs one (warp-uniform => broadcast) weight row slice
template<int NS>
__device__ __forceinline__ void fma2_ns8(ull* acc, const ull* pv, const float* wrow)
{
    ulonglong2 wa = *reinterpret_cast<const ulonglong2*>(wrow);
    ulonglong2 wb = *reinterpret_cast<const ulonglong2*>(wrow + 4);
    ull w0 = wa.x, w1 = wa.y, w2 = wb.x, w3 = wb.y;
    #pragma unroll
    for (int s = 0; s < NS; s++) {
        FMA2(acc[s*4+0], pv[s], w0, acc[s*4+0]);
        FMA2(acc[s*4+1], pv[s], w1, acc[s*4+1]);
        FMA2(acc[s*4+2], pv[s], w2, acc[s*4+2]);
        FMA2(acc[s*4+3], pv[s], w3, acc[s*4+3]);
    }
}

__device__ __forceinline__ void unp8(float o[8], const ull a[4])
{
    #pragma unroll
    for (int j = 0; j < 4; j++) {
        float2 p = unp2(a[j]);
        o[2*j] = p.x; o[2*j+1] = p.y;
    }
}

// ---------------- cp.async helpers ----------------
__device__ __forceinline__ void cpa16(unsigned dst, const float* src) {
    asm volatile("cp.async.ca.shared.global [%0], [%1], 16;" :: "r"(dst), "l"(src) : "memory");
}
#define CP_COMMIT() asm volatile("cp.async.commit_group;" ::: "memory")
#define CP_WAIT0()  asm volatile("cp.async.wait_group 0;" ::: "memory")

__device__ __forceinline__ void asyncW(unsigned dstB, const float* __restrict__ src) {
    for (int i = threadIdx.x; i < C * C / 4; i += NTH)
        cpa16(dstB + (unsigned)i * 16u, src + i * 4);
}

// ---------------------------------------------------------------------------
// Precompute: collapse C x C x C fctp tensors against rank-1 y-factors.
// ---------------------------------------------------------------------------
__global__ void precompute_kernel(const float* __restrict__ W00,
                                  const float* __restrict__ W11,
                                  const float* __restrict__ Wl2_0,
                                  const float* __restrict__ bl2_0,
                                  const float* __restrict__ Wl2_1)
{
    int idx = blockIdx.x * 256 + threadIdx.x;
    if (idx >= C * C) return;
    int u = idx / C;
    int w = idx - u * C;
    const float* p00 = W00 + u * C * C + w;
    const float* p11 = W11 + u * C * C + w;
    float a = 0.f, b = 0.f, c = 0.f;
    #pragma unroll 4
    for (int v = 0; v < C; v++) {
        float e00 = p00[v * C];
        float e11 = p11[v * C];
        a = fmaf(Wl2_0[v], e00, a);
        b = fmaf(bl2_0[v], e00, b);
        c = fmaf(Wl2_1[v], e11, c);
    }
    const float inv_s2 = 1.0f / sqrtf(2.0f * C * C);
    const float inv_s3 = 1.0f / sqrtf(3.0f);
    g_G0[idx] = a * inv_s2;
    g_G1[idx] = b * inv_s2;
    g_G2[idx] = c * inv_s2 * inv_s3;
}

// ---------------------------------------------------------------------------
// Fused main kernel. 384 threads (12 warps, 3/SMSP).
// Mapping: n = lane (node), v0 = warp_id*8 (warp-uniform column slice).
// ---------------------------------------------------------------------------
__global__ void __launch_bounds__(NTH, 1)
main_kernel(const float* __restrict__ nf, const float* __restrict__ pot,
            const float* __restrict__ Wl1_0, const float* __restrict__ Wl1_1,
            const float* __restrict__ Wm1, const float* __restrict__ Wm2,
            const float* __restrict__ Wm3, const float* __restrict__ Wm4,
            const float* __restrict__ Wo0a, const float* __restrict__ Wo0b,
            const float* __restrict__ Wo1a, const float* __restrict__ Wo1b,
            float* __restrict__ out, float silu_cst)
{
    extern __shared__ __align__(16) float sm[];
    float* B   = sm + OFF_B;
    float* B2  = sm + OFF_B2;
    float* X0  = sm + OFF_X0;
    float* X1  = sm + OFF_X1;
    float* Q   = sm + OFF_Q;
    float* F   = sm + OFF_F;
    float* G   = sm + OFF_G;
    float* H1  = sm + OFF_H1;
    float* H2  = sm + OFF_H2;
    float* POT = sm + OFF_POT;

    unsigned smb   = (unsigned)__cvta_generic_to_shared(sm);
    unsigned smbB  = smb + OFF_B  * 4u;
    unsigned smbB2 = smb + OFF_B2 * 4u;
    unsigned smbG  = smb + OFF_G  * 4u;

    const float INVC      = 1.0f / sqrtf((float)C);
    const float INV_SQRT3 = 1.0f / sqrtf(3.0f);
    const float NORM_OUT  = 1.0f / sqrtf(2.0f * C);

    const int tid  = threadIdx.x;
    const int base = blockIdx.x * TILE;
    const int n    = tid & 31;          // lane = node
    const int v0   = (tid >> 5) * 8;    // warp-uniform col slice (12 warps x 8)
    const int row  = base + n;

    // ---- prologue: async B<-Wl1_0, B2<-Wl1_1, G<-nf tile ----
    asyncW(smbB,  Wl1_0);
    asyncW(smbB2, Wl1_1);
    #pragma unroll
    for (int i = 0; i < 8; i++) {
        int idx = tid + i * NTH;
        int r = idx / 96;
        int c = idx - r * 96;
        cpa16(smbG + (unsigned)(r * GS + c * 4) * 4u,
              nf + (size_t)(base + r) * FOURC + c * 4);
    }
    CP_COMMIT();
    if (tid < TILE * 4) POT[(tid >> 2) * PS + (tid & 3)] = pot[base * 4 + tid];
    CP_WAIT0();
    __syncthreads();

    // ---- C1: x0 = nf0 @ Wl1_0 * invC ----
    {
        ull acc[4];
        #pragma unroll
        for (int j = 0; j < 4; j++) acc[j] = 0ULL;
        const float* gn = G + n * GS;
        #pragma unroll 2
        for (int u = 0; u < C; u += 4) {
            float4 a4 = *reinterpret_cast<const float4*>(gn + u);
            ull pv;
            pv = dup2(a4.x); fma2_ns8<1>(acc, &pv, B + (u + 0) * C + v0);
            pv = dup2(a4.y); fma2_ns8<1>(acc, &pv, B + (u + 1) * C + v0);
            pv = dup2(a4.z); fma2_ns8<1>(acc, &pv, B + (u + 2) * C + v0);
            pv = dup2(a4.w); fma2_ns8<1>(acc, &pv, B + (u + 3) * C + v0);
        }
        float o[8];
        unp8(o, acc);
        #pragma unroll
        for (int j = 0; j < 8; j++) X0[n * XS + v0 + j] = o[j] * INVC;
    }
    __syncthreads();
    asyncW(smbB, g_G0); CP_COMMIT();

    // ---- C2: x1_m = nf1_m @ Wl1_1 * invC (3 streams) ; q ----
    {
        ull acc[12];
        #pragma unroll
        for (int j = 0; j < 12; j++) acc[j] = 0ULL;
        const float* gn = G + n * GS + C;
        #pragma unroll 2
        for (int u = 0; u < C; u += 4) {
            float4 a0 = *reinterpret_cast<const float4*>(gn + u * 3);
            float4 a1 = *reinterpret_cast<const float4*>(gn + u * 3 + 4);
            float4 a2 = *reinterpret_cast<const float4*>(gn + u * 3 + 8);
            ull pv[3];
            pv[0]=dup2(a0.x); pv[1]=dup2(a0.y); pv[2]=dup2(a0.z);
            fma2_ns8<3>(acc, pv, B2 + (u + 0) * C + v0);
            pv[0]=dup2(a0.w); pv[1]=dup2(a1.x); pv[2]=dup2(a1.y);
            fma2_ns8<3>(acc, pv, B2 + (u + 1) * C + v0);
            pv[0]=dup2(a1.z); pv[1]=dup2(a1.w); pv[2]=dup2(a2.x);
            fma2_ns8<3>(acc, pv, B2 + (u + 2) * C + v0);
            pv[0]=dup2(a2.y); pv[1]=dup2(a2.z); pv[2]=dup2(a2.w);
            fma2_ns8<3>(acc, pv, B2 + (u + 3) * C + v0);
        }
        float p1 = POT[n*PS+1], p2 = POT[n*PS+2], p3 = POT[n*PS+3];
        float e0[8], e1[8], e2[8];
        unp8(e0, acc); unp8(e1, acc + 4); unp8(e2, acc + 8);
        #pragma unroll
        for (int j = 0; j < 8; j++) {
            float a0 = e0[j]*INVC, a1 = e1[j]*INVC, a2 = e2[j]*INVC;
            X1[0*X1P + n*XS + v0 + j] = a0;
            X1[1*X1P + n*XS + v0 + j] = a1;
            X1[2*X1P + n*XS + v0 + j] = a2;
            Q[n*XS + v0 + j] = a0*p1 + a1*p2 + a2*p3;
        }
    }
    CP_WAIT0(); __syncthreads();
    // prefetch G1 -> B2 and G2 -> G region (nf tile dead) under C3a
    asyncW(smbB2, g_G1);
    asyncW(smbG,  g_G2);
    CP_COMMIT();

    // ---- C3a: s0 = x0@G0 ----
    float s0f[8];
    {
        ull acc[4];
        #pragma unroll
        for (int j = 0; j < 4; j++) acc[j] = 0ULL;
        #pragma unroll 4
        for (int k = 0; k < C; k++) {
            ull pv = dup2(X0[n * XS + k]);
            fma2_ns8<1>(acc, &pv, B + k * C + v0);
        }
        unp8(s0f, acc);
    }
    CP_WAIT0(); __syncthreads();
    // prefetch MLP weights into B under fused C3b4
    {
        for (int i = tid; i < 384; i += NTH) cpa16(smbB + (unsigned)i * 16u, Wm1 + i * 4);
        for (int i = tid; i < 64;  i += NTH) cpa16(smbB + (unsigned)(1536 + i * 4) * 4u, Wm2 + i * 4);
        for (int i = tid; i < 64;  i += NTH) cpa16(smbB + (unsigned)(1792 + i * 4) * 4u, Wm3 + i * 4);
        for (int i = tid; i < 1536; i += NTH) cpa16(smbB + (unsigned)(2048 + i * 4) * 4u, Wm4 + i * 4);
        CP_COMMIT();
    }

    // ---- C3b4 (fused): s1 = x0@G1 (B2), s2 = q@G2 (G region) ;
    //      z = p0*s0 + s1 ; F = (z + s2)^2 ----
    {
        ull a1[4], a2[4];
        #pragma unroll
        for (int j = 0; j < 4; j++) { a1[j] = 0ULL; a2[j] = 0ULL; }
        #pragma unroll 4
        for (int k = 0; k < C; k++) {
            ull pvx = dup2(X0[n * XS + k]);
            ull pvq = dup2(Q[n * XS + k]);
            fma2_ns8<1>(a1, &pvx, B2 + k * C + v0);
            fma2_ns8<1>(a2, &pvq, G + k * C + v0);
        }
        float s1f[8], s2f[8];
        unp8(s1f, a1); unp8(s2f, a2);
        float p0 = POT[n*PS];
        #pragma unroll
        for (int j = 0; j < 8; j++) {
            float z = p0 * s0f[j] + s1f[j] + s2f[j];
            F[n * XS + v0 + j] = z * z;
        }
    }
    CP_WAIT0(); __syncthreads();
    asyncW(smbB2, Wo1a); CP_COMMIT();   // under C5 (long)

    // ---- C5: MLP F -> tp_w (G, stride TS) ; MLP weights in B ----
    {
        const float cst = silu_cst;
        for (int idx = tid; idx < TILE * 16; idx += NTH) {
            int nn = idx >> 4, j = idx & 15;
            const float* nr = F + nn * XS;
            float s = 0.f;
            #pragma unroll 8
            for (int u = 0; u < C; u++) s = fmaf(nr[u], B[u * 16 + j], s);
            s *= INVC;
            H1[nn * HS + j] = cst * s / (1.0f + expf(-s));
        }
        __syncthreads();
        for (int idx = tid; idx < TILE * 16; idx += NTH) {
            int nn = idx >> 4, j = idx & 15;
            float s = 0.f;
            #pragma unroll
            for (int k = 0; k < 16; k++) s = fmaf(H1[nn * HS + k], B[1536 + k * 16 + j], s);
            s *= 0.25f;
            H2[nn * HS + j] = cst * s / (1.0f + expf(-s));
        }
        __syncthreads();
        for (int idx = tid; idx < TILE * 16; idx += NTH) {
            int nn = idx >> 4, j = idx & 15;
            float s = 0.f;
            #pragma unroll
            for (int k = 0; k < 16; k++) s = fmaf(H2[nn * HS + k], B[1792 + k * 16 + j], s);
            s *= 0.25f;
            H1[nn * HS + j] = cst * s / (1.0f + expf(-s));
        }
        __syncthreads();
        // tp_w: lane = node, warp cols v0, 4 sections (G2 dead; overwrite region)
        float h[16];
        #pragma unroll
        for (int k = 0; k < 16; k++) h[k] = H1[n * HS + k];
        ull a[16];
        #pragma unroll
        for (int j = 0; j < 16; j++) a[j] = 0ULL;
        #pragma unroll
        for (int k = 0; k < 16; k++) {
            ull pv = dup2(h[k]);
            #pragma unroll
            for (int sec = 0; sec < 4; sec++)
                fma2_ns8<1>(a + sec * 4, &pv, B + 2048 + k * FOURC + sec * C + v0);
        }
        #pragma unroll
        for (int sec = 0; sec < 4; sec++) {
            float o[8];
            unp8(o, a + sec * 4);
            float* dst = G + n * TS + sec * C + v0;
            #pragma unroll
            for (int j = 0; j < 8; j++) dst[j] = o[j] * 0.25f;
        }
    }
    CP_WAIT0(); __syncthreads();
    asyncW(smbB, Wo1b); CP_COMMIT();    // under C6

    const float p0 = POT[n*PS];
    const float p1 = POT[n*PS+1], p2 = POT[n*PS+2], p3 = POT[n*PS+3];

    // ---- C6: sa = (w01*x0) @ Wo1a (B2) ----
    float saf[8];
    {
        ull acc[4];
        #pragma unroll
        for (int j = 0; j < 4; j++) acc[j] = 0ULL;
        #pragma unroll 4
        for (int k = 0; k < C; k++) {
            ull pv = dup2(G[n * TS + C + k] * X0[n * XS + k]);
            fma2_ns8<1>(acc, &pv, B2 + k * C + v0);
        }
        unp8(saf, acc);
    }
    CP_WAIT0(); __syncthreads();
    asyncW(smbB2, Wo0a); CP_COMMIT();   // under C7

    // ---- C7: sb_m = (w10*x1_m) @ Wo1b (B, 3 streams) ; write out1 ----
    {
        ull acc[12];
        #pragma unroll
        for (int j = 0; j < 12; j++) acc[j] = 0ULL;
        #pragma unroll 2
        for (int k = 0; k < C; k++) {
            float w = G[n * TS + 2 * C + k];
            ull pv[3];
            pv[0] = dup2(w * X1[0*X1P + n*XS + k]);
            pv[1] = dup2(w * X1[1*X1P + n*XS + k]);
            pv[2] = dup2(w * X1[2*X1P + n*XS + k]);
            fma2_ns8<3>(acc, pv, B + k * C + v0);
        }
        float e0[8], e1[8], e2[8];
        unp8(e0, acc); unp8(e1, acc + 4); unp8(e2, acc + 8);
        float o[24];
        #pragma unroll
        for (int j = 0; j < 8; j++) {
            float s = saf[j];
            o[j*3+0] = (p1 * s + p0 * e0[j]) * NORM_OUT;
            o[j*3+1] = (p2 * s + p0 * e1[j]) * NORM_OUT;
            o[j*3+2] = (p3 * s + p0 * e2[j]) * NORM_OUT;
        }
        float4* d = reinterpret_cast<float4*>(out + (size_t)row * FOURC + C + v0 * 3);
        #pragma unroll
        for (int i = 0; i < 6; i++) d[i] = reinterpret_cast<const float4*>(o)[i];
    }
    CP_WAIT0(); __syncthreads();
    asyncW(smbB, Wo0b); CP_COMMIT();    // under C8a

    // ---- C8a: o1 = (w00*x0) @ Wo0a (B2) ----
    float o1f[8];
    {
        ull acc[4];
        #pragma unroll
        for (int j = 0; j < 4; j++) acc[j] = 0ULL;
        #pragma unroll 4
        for (int k = 0; k < C; k++) {
            ull pv = dup2(G[n * TS + k] * X0[n * XS + k]);
            fma2_ns8<1>(acc, &pv, B2 + k * C + v0);
        }
        unp8(o1f, acc);
    }
    CP_WAIT0(); __syncthreads();

    // ---- C8b: o2 = (w11*q) @ Wo0b (B) ; out0 ----
    {
        ull acc[4];
        #pragma unroll
        for (int j = 0; j < 4; j++) acc[j] = 0ULL;
        #pragma unroll 4
        for (int k = 0; k < C; k++) {
            ull pv = dup2(G[n * TS + 3 * C + k] * Q[n * XS + k]);
            fma2_ns8<1>(acc, &pv, B + k * C + v0);
        }
        float o2f[8];
        unp8(o2f, acc);
        float o[8];
        #pragma unroll
        for (int j = 0; j < 8; j++)
            o[j] = (p0 * o1f[j] + o2f[j] * INV_SQRT3) * NORM_OUT;
        float4* d = reinterpret_cast<float4*>(out + (size_t)row * FOURC + v0);
        #pragma unroll
        for (int i = 0; i < 2; i++) d[i] = reinterpret_cast<const float4*>(o)[i];
    }
}

// ---------------------------------------------------------------------------
extern "C" void kernel_launch(void* const* d_in, const int* in_sizes, int n_in,
                              void* d_out, int out_size)
{
    const float* nf    = (const float*)d_in[0];
    const float* pot   = (const float*)d_in[1];
    const float* Wl1_0 = (const float*)d_in[2];
    const float* Wl1_1 = (const float*)d_in[3];
    const float* Wl2_0 = (const float*)d_in[4];
    const float* bl2_0 = (const float*)d_in[5];
    const float* Wl2_1 = (const float*)d_in[6];
    const float* W00   = (const float*)d_in[7];
    const float* W11   = (const float*)d_in[8];
    const float* Wm1   = (const float*)d_in[9];
    const float* Wm2   = (const float*)d_in[10];
    const float* Wm3   = (const float*)d_in[11];
    const float* Wm4   = (const float*)d_in[12];
    const float* Wo0a  = (const float*)d_in[13];
    const float* Wo0b  = (const float*)d_in[14];
    const float* Wo1a  = (const float*)d_in[15];
    const float* Wo1b  = (const float*)d_in[16];
    float* out = (float*)d_out;

    // SILU_CST: input-independent — replicate reference quadrature on host (f64).
    double dz = 24.0 / 200000.0;
    double m2 = 0.0;
    const double inv_sqrt2pi = 0.3989422804014326779399460599343818684759;
    for (int i = 0; i <= 200000; i++) {
        double z = -12.0 + i * dz;
        double s = z / (1.0 + exp(-z));
        m2 += s * s * exp(-0.5 * z * z) * inv_sqrt2pi;
    }
    m2 *= dz;
    float silu_cst = (float)(1.0 / sqrt(m2));

    cudaFuncSetAttribute(main_kernel, cudaFuncAttributeMaxDynamicSharedMemorySize, SMEM_BYTES);

    precompute_kernel<<<36, 256>>>(W00, W11, Wl2_0, bl2_0, Wl2_1);
    main_kernel<<<NCTAS, NTH, SMEM_BYTES>>>(nf, pot, Wl1_0, Wl1_1,
                                            Wm1, Wm2, Wm3, Wm4,
                                            Wo0a, Wo0b, Wo1a, Wo1b, out, silu_cst);
}

// round 13
// speedup vs baseline: 1.0315x; 1.0315x over previous
#include <cuda_runtime.h>
#include <math.h>

#define C 96
#define FOURC 384
#define NN 4096
#define TILE 32
#define NTH 256
#define NCTAS (NN / TILE)   // 128

typedef unsigned long long ull;

#define XS 97               // padded stride for X0/X1/Q/F
#define GS 388              // nf tile rows (16B aligned for cp.async)
#define TS 385              // tp_w rows (odd -> conflict-free scalar)
#define HS 17               // H1/H2 row stride
#define PS 5                // POT row stride
#define X1P (TILE * XS)

// ---------------- shared memory layout (floats) ----------------
#define OFF_B    0          // 9216 : weight buffer A
#define OFF_B2   9216       // 9216 : weight buffer B
#define OFF_X0   18432      // 3104
#define OFF_X1   21536      // 9312
#define OFF_Q    30848      // 3104
#define OFF_F    33952      // 3104
#define OFF_G    37056      // 12416 : nf tile (388), then G2 (96x96), then tp_w (385)
#define OFF_H1   49472      // 544
#define OFF_H2   50016      // 544
#define OFF_POT  50560      // 160
#define SMEM_FLOATS 50720
#define SMEM_BYTES (SMEM_FLOATS * 4)   // 202880 B -> 1 CTA/SM, 8 warps

// ---------------- device scratch ----------------
__device__ __align__(16) float g_G0[C * C];
__device__ __align__(16) float g_G1[C * C];
__device__ __align__(16) float g_G2[C * C];

// ---------------- f32x2 helpers ----------------
__device__ __forceinline__ ull dup2(float a) {
    ull r;
    asm("mov.b64 %0, {%1, %1};" : "=l"(r) : "f"(a));
    return r;
}
__device__ __forceinline__ float2 unp2(ull v) {
    float2 r;
    asm("mov.b64 {%0, %1}, %2;" : "=f"(r.x), "=f"(r.y) : "l"(v));
    return r;
}
#define FMA2(d, a, b, cc) asm("fma.rn.f32x2 %0, %1, %2, %3;" : "=l"(d) : "l"(a), "l"(b), "l"(cc))

// NS activation streams x 12 cols vs one (warp-uniform => broadcast) weight row slice
template<int NS>
__device__ __forceinline__ void fma2_ns(ull* acc, const ull* pv, const float* wrow)
{
    ulonglong2 wa = *reinterpret_cast<const ulonglong2*>(wrow);
    ulonglong2 wb = *reinterpret_cast<const ulonglong2*>(wrow + 4);
    ulonglong2 wc = *reinterpret_cast<const ulonglong2*>(wrow + 8);
    ull w0 = wa.x, w1 = wa.y, w2 = wb.x, w3 = wb.y, w4 = wc.x, w5 = wc.y;
    #pragma unroll
    for (int s = 0; s < NS; s++) {
        FMA2(acc[s*6+0], pv[s], w0, acc[s*6+0]);
        FMA2(acc[s*6+1], pv[s], w1, acc[s*6+1]);
        FMA2(acc[s*6+2], pv[s], w2, acc[s*6+2]);
        FMA2(acc[s*6+3], pv[s], w3, acc[s*6+3]);
        FMA2(acc[s*6+4], pv[s], w4, acc[s*6+4]);
        FMA2(acc[s*6+5], pv[s], w5, acc[s*6+5]);
    }
}

__device__ __forceinline__ void unp12(float o[12], const ull a[6])
{
    #pragma unroll
    for (int j = 0; j < 6; j++) {
        float2 p = unp2(a[j]);
        o[2*j] = p.x; o[2*j+1] = p.y;
    }
}

// ---------------- cp.async helpers ----------------
__device__ __forceinline__ void cpa16(unsigned dst, const float* src) {
    asm volatile("cp.async.ca.shared.global [%0], [%1], 16;" :: "r"(dst), "l"(src) : "memory");
}
#define CP_COMMIT() asm volatile("cp.async.commit_group;" ::: "memory")
#define CP_WAIT0()  asm volatile("cp.async.wait_group 0;" ::: "memory")

__device__ __forceinline__ void asyncW(unsigned dstB, const float* __restrict__ src) {
    for (int i = threadIdx.x; i < C * C / 4; i += NTH)
        cpa16(dstB + (unsigned)i * 16u, src + i * 4);
}

// ---------------------------------------------------------------------------
// Precompute: collapse C x C x C fctp tensors against rank-1 y-factors.
// ---------------------------------------------------------------------------
__global__ void precompute_kernel(const float* __restrict__ W00,
                                  const float* __restrict__ W11,
                                  const float* __restrict__ Wl2_0,
                                  const float* __restrict__ bl2_0,
                                  const float* __restrict__ Wl2_1)
{
    int idx = blockIdx.x * 256 + threadIdx.x;
    if (idx >= C * C) return;
    int u = idx / C;
    int w = idx - u * C;
    const float* p00 = W00 + u * C * C + w;
    const float* p11 = W11 + u * C * C + w;
    float a = 0.f, b = 0.f, c = 0.f;
    #pragma unroll 4
    for (int v = 0; v < C; v++) {
        float e00 = p00[v * C];
        float e11 = p11[v * C];
        a = fmaf(Wl2_0[v], e00, a);
        b = fmaf(bl2_0[v], e00, b);
        c = fmaf(Wl2_1[v], e11, c);
    }
    const float inv_s2 = 1.0f / sqrtf(2.0f * C * C);
    const float inv_s3 = 1.0f / sqrtf(3.0f);
    g_G0[idx] = a * inv_s2;
    g_G1[idx] = b * inv_s2;
    g_G2[idx] = c * inv_s2 * inv_s3;
}

// ---------------------------------------------------------------------------
// Fused main kernel. 256 threads (8 warps, 2/SMSP).
// Mapping: n = lane (node), v0 = warp_id*12 (warp-uniform column slice).
// Schedule: R12's fused pipeline (one fewer pass/barrier than R11).
// ---------------------------------------------------------------------------
__global__ void __launch_bounds__(NTH, 1)
main_kernel(const float* __restrict__ nf, const float* __restrict__ pot,
            const float* __restrict__ Wl1_0, const float* __restrict__ Wl1_1,
            const float* __restrict__ Wm1, const float* __restrict__ Wm2,
            const float* __restrict__ Wm3, const float* __restrict__ Wm4,
            const float* __restrict__ Wo0a, const float* __restrict__ Wo0b,
            const float* __restrict__ Wo1a, const float* __restrict__ Wo1b,
            float* __restrict__ out, float silu_cst)
{
    extern __shared__ __align__(16) float sm[];
    float* B   = sm + OFF_B;
    float* B2  = sm + OFF_B2;
    float* X0  = sm + OFF_X0;
    float* X1  = sm + OFF_X1;
    float* Q   = sm + OFF_Q;
    float* F   = sm + OFF_F;
    float* G   = sm + OFF_G;
    float* H1  = sm + OFF_H1;
    float* H2  = sm + OFF_H2;
    float* POT = sm + OFF_POT;

    unsigned smb   = (unsigned)__cvta_generic_to_shared(sm);
    unsigned smbB  = smb + OFF_B  * 4u;
    unsigned smbB2 = smb + OFF_B2 * 4u;
    unsigned smbG  = smb + OFF_G  * 4u;

    const float INVC      = 1.0f / sqrtf((float)C);
    const float INV_SQRT3 = 1.0f / sqrtf(3.0f);
    const float NORM_OUT  = 1.0f / sqrtf(2.0f * C);

    const int tid  = threadIdx.x;
    const int base = blockIdx.x * TILE;
    const int n    = tid & 31;          // lane = node
    const int v0   = (tid >> 5) * 12;   // warp-uniform col slice (8 warps x 12)
    const int row  = base + n;

    // ---- prologue: async B<-Wl1_0, B2<-Wl1_1, G<-nf tile ----
    asyncW(smbB,  Wl1_0);
    asyncW(smbB2, Wl1_1);
    #pragma unroll
    for (int i = 0; i < 12; i++) {
        int idx = tid + i * NTH;
        int r = idx / 96;
        int c = idx - r * 96;
        cpa16(smbG + (unsigned)(r * GS + c * 4) * 4u,
              nf + (size_t)(base + r) * FOURC + c * 4);
    }
    CP_COMMIT();
    if (tid < TILE * 4) POT[(tid >> 2) * PS + (tid & 3)] = pot[base * 4 + tid];
    CP_WAIT0();
    __syncthreads();

    // ---- C1: x0 = nf0 @ Wl1_0 * invC ----
    {
        ull acc[6];
        #pragma unroll
        for (int j = 0; j < 6; j++) acc[j] = 0ULL;
        const float* gn = G + n * GS;
        #pragma unroll 2
        for (int u = 0; u < C; u += 4) {
            float4 a4 = *reinterpret_cast<const float4*>(gn + u);
            ull pv;
            pv = dup2(a4.x); fma2_ns<1>(acc, &pv, B + (u + 0) * C + v0);
            pv = dup2(a4.y); fma2_ns<1>(acc, &pv, B + (u + 1) * C + v0);
            pv = dup2(a4.z); fma2_ns<1>(acc, &pv, B + (u + 2) * C + v0);
            pv = dup2(a4.w); fma2_ns<1>(acc, &pv, B + (u + 3) * C + v0);
        }
        float o[12];
        unp12(o, acc);
        #pragma unroll
        for (int j = 0; j < 12; j++) X0[n * XS + v0 + j] = o[j] * INVC;
    }
    __syncthreads();
    asyncW(smbB, g_G0); CP_COMMIT();   // G0 -> B under C2

    // ---- C2: x1_m = nf1_m @ Wl1_1 * invC (3 streams) ; q ----
    {
        ull acc[18];
        #pragma unroll
        for (int j = 0; j < 18; j++) acc[j] = 0ULL;
        const float* gn = G + n * GS + C;
        #pragma unroll 2
        for (int u = 0; u < C; u += 4) {
            float4 a0 = *reinterpret_cast<const float4*>(gn + u * 3);
            float4 a1 = *reinterpret_cast<const float4*>(gn + u * 3 + 4);
            float4 a2 = *reinterpret_cast<const float4*>(gn + u * 3 + 8);
            ull pv[3];
            pv[0]=dup2(a0.x); pv[1]=dup2(a0.y); pv[2]=dup2(a0.z);
            fma2_ns<3>(acc, pv, B2 + (u + 0) * C + v0);
            pv[0]=dup2(a0.w); pv[1]=dup2(a1.x); pv[2]=dup2(a1.y);
            fma2_ns<3>(acc, pv, B2 + (u + 1) * C + v0);
            pv[0]=dup2(a1.z); pv[1]=dup2(a1.w); pv[2]=dup2(a2.x);
            fma2_ns<3>(acc, pv, B2 + (u + 2) * C + v0);
            pv[0]=dup2(a2.y); pv[1]=dup2(a2.z); pv[2]=dup2(a2.w);
            fma2_ns<3>(acc, pv, B2 + (u + 3) * C + v0);
        }
        float p1 = POT[n*PS+1], p2 = POT[n*PS+2], p3 = POT[n*PS+3];
        float e0[12], e1[12], e2[12];
        unp12(e0, acc); unp12(e1, acc + 6); unp12(e2, acc + 12);
        #pragma unroll
        for (int j = 0; j < 12; j++) {
            float a0 = e0[j]*INVC, a1 = e1[j]*INVC, a2 = e2[j]*INVC;
            X1[0*X1P + n*XS + v0 + j] = a0;
            X1[1*X1P + n*XS + v0 + j] = a1;
            X1[2*X1P + n*XS + v0 + j] = a2;
            Q[n*XS + v0 + j] = a0*p1 + a1*p2 + a2*p3;
        }
    }
    CP_WAIT0(); __syncthreads();
    // prefetch G1 -> B2 and G2 -> G region (nf tile dead) under C3a
    asyncW(smbB2, g_G1);
    asyncW(smbG,  g_G2);
    CP_COMMIT();

    // ---- C3a: s0 = x0@G0 ----
    float s0f[12];
    {
        ull acc[6];
        #pragma unroll
        for (int j = 0; j < 6; j++) acc[j] = 0ULL;
        #pragma unroll 4
        for (int k = 0; k < C; k++) {
            ull pv = dup2(X0[n * XS + k]);
            fma2_ns<1>(acc, &pv, B + k * C + v0);
        }
        unp12(s0f, acc);
    }
    CP_WAIT0(); __syncthreads();
    // prefetch MLP weights into B under fused C3b4
    {
        for (int i = tid; i < 384; i += NTH) cpa16(smbB + (unsigned)i * 16u, Wm1 + i * 4);
        for (int i = tid; i < 64;  i += NTH) cpa16(smbB + (unsigned)(1536 + i * 4) * 4u, Wm2 + i * 4);
        for (int i = tid; i < 64;  i += NTH) cpa16(smbB + (unsigned)(1792 + i * 4) * 4u, Wm3 + i * 4);
        for (int i = tid; i < 1536; i += NTH) cpa16(smbB + (unsigned)(2048 + i * 4) * 4u, Wm4 + i * 4);
        CP_COMMIT();
    }

    // ---- C3b4 (fused): s1 = x0@G1 (B2), s2 = q@G2 (G region) ;
    //      z = p0*s0 + s1 + s2 ; F = z^2 ----
    {
        ull a1[6], a2[6];
        #pragma unroll
        for (int j = 0; j < 6; j++) { a1[j] = 0ULL; a2[j] = 0ULL; }
        #pragma unroll 4
        for (int k = 0; k < C; k++) {
            ull pvx = dup2(X0[n * XS + k]);
            ull pvq = dup2(Q[n * XS + k]);
            fma2_ns<1>(a1, &pvx, B2 + k * C + v0);
            fma2_ns<1>(a2, &pvq, G + k * C + v0);
        }
        float s1f[12], s2f[12];
        unp12(s1f, a1); unp12(s2f, a2);
        float p0 = POT[n*PS];
        #pragma unroll
        for (int j = 0; j < 12; j++) {
            float z = p0 * s0f[j] + s1f[j] + s2f[j];
            F[n * XS + v0 + j] = z * z;
        }
    }
    CP_WAIT0(); __syncthreads();
    asyncW(smbB2, Wo1a); CP_COMMIT();   // under C5 (long)

    // ---- C5: MLP F -> tp_w (G, stride TS) ; MLP weights in B ----
    {
        const float cst = silu_cst;
        #pragma unroll
        for (int idx = tid; idx < TILE * 16; idx += NTH) {
            int nn = idx >> 4, j = idx & 15;
            const float* nr = F + nn * XS;
            float s = 0.f;
            #pragma unroll 8
            for (int u = 0; u < C; u++) s = fmaf(nr[u], B[u * 16 + j], s);
            s *= INVC;
            H1[nn * HS + j] = cst * s / (1.0f + expf(-s));
        }
        __syncthreads();
        #pragma unroll
        for (int idx = tid; idx < TILE * 16; idx += NTH) {
            int nn = idx >> 4, j = idx & 15;
            float s = 0.f;
            #pragma unroll
            for (int k = 0; k < 16; k++) s = fmaf(H1[nn * HS + k], B[1536 + k * 16 + j], s);
            s *= 0.25f;
            H2[nn * HS + j] = cst * s / (1.0f + expf(-s));
        }
        __syncthreads();
        #pragma unroll
        for (int idx = tid; idx < TILE * 16; idx += NTH) {
            int nn = idx >> 4, j = idx & 15;
            float s = 0.f;
            #pragma unroll
            for (int k = 0; k < 16; k++) s = fmaf(H2[nn * HS + k], B[1792 + k * 16 + j], s);
            s *= 0.25f;
            H1[nn * HS + j] = cst * s / (1.0f + expf(-s));
        }
        __syncthreads();
        // tp_w: lane = node, warp cols v0, 4 sections (G2 dead; overwrite region)
        float h[16];
        #pragma unroll
        for (int k = 0; k < 16; k++) h[k] = H1[n * HS + k];
        ull a[24];
        #pragma unroll
        for (int j = 0; j < 24; j++) a[j] = 0ULL;
        #pragma unroll
        for (int k = 0; k < 16; k++) {
            ull pv = dup2(h[k]);
            #pragma unroll
            for (int sec = 0; sec < 4; sec++)
                fma2_ns<1>(a + sec * 6, &pv, B + 2048 + k * FOURC + sec * C + v0);
        }
        __syncthreads();   // all G2 reads (C3b4) complete before overwrite
        #pragma unroll
        for (int sec = 0; sec < 4; sec++) {
            float o[12];
            unp12(o, a + sec * 6);
            float* dst = G + n * TS + sec * C + v0;
            #pragma unroll
            for (int j = 0; j < 12; j++) dst[j] = o[j] * 0.25f;
        }
    }
    CP_WAIT0(); __syncthreads();
    asyncW(smbB, Wo1b); CP_COMMIT();    // under C6

    const float p0 = POT[n*PS];
    const float p1 = POT[n*PS+1], p2 = POT[n*PS+2], p3 = POT[n*PS+3];

    // ---- C6: sa = (w01*x0) @ Wo1a (B2) ----
    float saf[12];
    {
        ull acc[6];
        #pragma unroll
        for (int j = 0; j < 6; j++) acc[j] = 0ULL;
        #pragma unroll 4
        for (int k = 0; k < C; k++) {
            ull pv = dup2(G[n * TS + C + k] * X0[n * XS + k]);
            fma2_ns<1>(acc, &pv, B2 + k * C + v0);
        }
        unp12(saf, acc);
    }
    CP_WAIT0(); __syncthreads();
    asyncW(smbB2, Wo0a); CP_COMMIT();   // under C7

    // ---- C7: sb_m = (w10*x1_m) @ Wo1b (B, 3 streams) ; write out1 ----
    {
        ull acc[18];
        #pragma unroll
        for (int j = 0; j < 18; j++) acc[j] = 0ULL;
        #pragma unroll 2
        for (int k = 0; k < C; k++) {
            float w = G[n * TS + 2 * C + k];
            ull pv[3];
            pv[0] = dup2(w * X1[0*X1P + n*XS + k]);
            pv[1] = dup2(w * X1[1*X1P + n*XS + k]);
            pv[2] = dup2(w * X1[2*X1P + n*XS + k]);
            fma2_ns<3>(acc, pv, B + k * C + v0);
        }
        float e0[12], e1[12], e2[12];
        unp12(e0, acc); unp12(e1, acc + 6); unp12(e2, acc + 12);
        float o[36];
        #pragma unroll
        for (int j = 0; j < 12; j++) {
            float s = saf[j];
            o[j*3+0] = (p1 * s + p0 * e0[j]) * NORM_OUT;
            o[j*3+1] = (p2 * s + p0 * e1[j]) * NORM_OUT;
            o[j*3+2] = (p3 * s + p0 * e2[j]) * NORM_OUT;
        }
        float4* d = reinterpret_cast<float4*>(out + (size_t)row * FOURC + C + v0 * 3);
        #pragma unroll
        for (int i = 0; i < 9; i++) d[i] = reinterpret_cast<const float4*>(o)[i];
    }
    CP_WAIT0(); __syncthreads();
    asyncW(smbB, Wo0b); CP_COMMIT();    // under C8a

    // ---- C8a: o1 = (w00*x0) @ Wo0a (B2) ----
    float o1f[12];
    {
        ull acc[6];
        #pragma unroll
        for (int j = 0; j < 6; j++) acc[j] = 0ULL;
        #pragma unroll 4
        for (int k = 0; k < C; k++) {
            ull pv = dup2(G[n * TS + k] * X0[n * XS + k]);
            fma2_ns<1>(acc, &pv, B2 + k * C + v0);
        }
        unp12(o1f, acc);
    }
    CP_WAIT0(); __syncthreads();

    // ---- C8b: o2 = (w11*q) @ Wo0b (B) ; out0 ----
    {
        ull acc[6];
        #pragma unroll
        for (int j = 0; j < 6; j++) acc[j] = 0ULL;
        #pragma unroll 4
        for (int k = 0; k < C; k++) {
            ull pv = dup2(G[n * TS + 3 * C + k] * Q[n * XS + k]);
            fma2_ns<1>(acc, &pv, B + k * C + v0);
        }
        float o2f[12];
        unp12(o2f, acc);
        float o[12];
        #pragma unroll
        for (int j = 0; j < 12; j++)
            o[j] = (p0 * o1f[j] + o2f[j] * INV_SQRT3) * NORM_OUT;
        float4* d = reinterpret_cast<float4*>(out + (size_t)row * FOURC + v0);
        #pragma unroll
        for (int i = 0; i < 3; i++) d[i] = reinterpret_cast<const float4*>(o)[i];
    }
}

// ---------------------------------------------------------------------------
extern "C" void kernel_launch(void* const* d_in, const int* in_sizes, int n_in,
                              void* d_out, int out_size)
{
    const float* nf    = (const float*)d_in[0];
    const float* pot   = (const float*)d_in[1];
    const float* Wl1_0 = (const float*)d_in[2];
    const float* Wl1_1 = (const float*)d_in[3];
    const float* Wl2_0 = (const float*)d_in[4];
    const float* bl2_0 = (const float*)d_in[5];
    const float* Wl2_1 = (const float*)d_in[6];
    const float* W00   = (const float*)d_in[7];
    const float* W11   = (const float*)d_in[8];
    const float* Wm1   = (const float*)d_in[9];
    const float* Wm2   = (const float*)d_in[10];
    const float* Wm3   = (const float*)d_in[11];
    const float* Wm4   = (const float*)d_in[12];
    const float* Wo0a  = (const float*)d_in[13];
    const float* Wo0b  = (const float*)d_in[14];
    const float* Wo1a  = (const float*)d_in[15];
    const float* Wo1b  = (const float*)d_in[16];
    float* out = (float*)d_out;

    // SILU_CST: input-independent — replicate reference quadrature on host (f64).
    double dz = 24.0 / 200000.0;
    double m2 = 0.0;
    const double inv_sqrt2pi = 0.3989422804014326779399460599343818684759;
    for (int i = 0; i <= 200000; i++) {
        double z = -12.0 + i * dz;
        double s = z / (1.0 + exp(-z));
        m2 += s * s * exp(-0.5 * z * z) * inv_sqrt2pi;
    }
    m2 *= dz;
    float silu_cst = (float)(1.0 / sqrt(m2));

    cudaFuncSetAttribute(main_kernel, cudaFuncAttributeMaxDynamicSharedMemorySize, SMEM_BYTES);

    precompute_kernel<<<36, 256>>>(W00, W11, Wl2_0, bl2_0, Wl2_1);
    main_kernel<<<NCTAS, NTH, SMEM_BYTES>>>(nf, pot, Wl1_0, Wl1_1,
                                            Wm1, Wm2, Wm3, Wm4,
                                            Wo0a, Wo0b, Wo1a, Wo1b, out, silu_cst);
}

// round 16
// speedup vs baseline: 1.1599x; 1.1244x over previous
#include <cuda_runtime.h>
#include <math.h>

#define C 96
#define FOURC 384
#define NN 4096
#define TILE 32
#define NTH 256
#define NCTAS (NN / TILE)   // 128

typedef unsigned long long ull;

#define XS 97               // padded stride for X0/X1/Q/F
#define GS 388              // nf tile rows (16B aligned for cp.async)
#define TS 385              // tp_w rows (odd -> conflict-free scalar)
#define HS 17               // H1/H2 row stride
#define PS 5                // POT row stride
#define X1P (TILE * XS)

// ---------------- shared memory layout (floats) ----------------
#define OFF_B    0          // 9216 : weight buffer A
#define OFF_B2   9216       // 9216 : weight buffer B
#define OFF_X0   18432      // 3104
#define OFF_X1   21536      // 9312
#define OFF_Q    30848      // 3104
#define OFF_F    33952      // 3104
#define OFF_G    37056      // 12416 : nf tile (388), then G2 (96x96), then tp_w (385)
#define OFF_H1   49472      // 544
#define OFF_H2   50016      // 544
#define OFF_POT  50560      // 160
#define SMEM_FLOATS 50720
#define SMEM_BYTES (SMEM_FLOATS * 4)   // 202880 B -> 1 CTA/SM, 8 warps

// ---------------- device scratch ----------------
__device__ __align__(16) float g_G0[C * C];
__device__ __align__(16) float g_G1[C * C];
__device__ __align__(16) float g_G2[C * C];

// ---------------- f32x2 helpers ----------------
__device__ __forceinline__ ull dup2(float a) {
    ull r;
    asm("mov.b64 %0, {%1, %1};" : "=l"(r) : "f"(a));
    return r;
}
__device__ __forceinline__ float2 unp2(ull v) {
    float2 r;
    asm("mov.b64 {%0, %1}, %2;" : "=f"(r.x), "=f"(r.y) : "l"(v));
    return r;
}
#define FMA2(d, a, b, cc) asm("fma.rn.f32x2 %0, %1, %2, %3;" : "=l"(d) : "l"(a), "l"(b), "l"(cc))

// NS activation streams x 12 cols vs one (warp-uniform => broadcast) weight row slice
template<int NS>
__device__ __forceinline__ void fma2_ns(ull* acc, const ull* pv, const float* wrow)
{
    ulonglong2 wa = *reinterpret_cast<const ulonglong2*>(wrow);
    ulonglong2 wb = *reinterpret_cast<const ulonglong2*>(wrow + 4);
    ulonglong2 wc = *reinterpret_cast<const ulonglong2*>(wrow + 8);
    ull w0 = wa.x, w1 = wa.y, w2 = wb.x, w3 = wb.y, w4 = wc.x, w5 = wc.y;
    #pragma unroll
    for (int s = 0; s < NS; s++) {
        FMA2(acc[s*6+0], pv[s], w0, acc[s*6+0]);
        FMA2(acc[s*6+1], pv[s], w1, acc[s*6+1]);
        FMA2(acc[s*6+2], pv[s], w2, acc[s*6+2]);
        FMA2(acc[s*6+3], pv[s], w3, acc[s*6+3]);
        FMA2(acc[s*6+4], pv[s], w4, acc[s*6+4]);
        FMA2(acc[s*6+5], pv[s], w5, acc[s*6+5]);
    }
}

__device__ __forceinline__ void unp12(float o[12], const ull a[6])
{
    #pragma unroll
    for (int j = 0; j < 6; j++) {
        float2 p = unp2(a[j]);
        o[2*j] = p.x; o[2*j+1] = p.y;
    }
}

// ---------------- cp.async helpers ----------------
__device__ __forceinline__ void cpa16(unsigned dst, const float* src) {
    asm volatile("cp.async.ca.shared.global [%0], [%1], 16;" :: "r"(dst), "l"(src) : "memory");
}
#define CP_COMMIT() asm volatile("cp.async.commit_group;" ::: "memory")
#define CP_WAIT0()  asm volatile("cp.async.wait_group 0;" ::: "memory")

__device__ __forceinline__ void asyncW(unsigned dstB, const float* __restrict__ src) {
    for (int i = threadIdx.x; i < C * C / 4; i += NTH)
        cpa16(dstB + (unsigned)i * 16u, src + i * 4);
}

// ---------------------------------------------------------------------------
// Precompute (fast): one CTA per u. Coalesced-load W00[u,:,:], W11[u,:,:]
// (36 KB each) into smem, then 96 threads compute the three v-dot-products.
// ---------------------------------------------------------------------------
#define PC_NTH 256
#define PC_SMEM ((2 * C * C + 3 * C) * 4)   // 74880 B
__global__ void __launch_bounds__(PC_NTH)
precompute_kernel(const float* __restrict__ W00,
                  const float* __restrict__ W11,
                  const float* __restrict__ Wl2_0,
                  const float* __restrict__ bl2_0,
                  const float* __restrict__ Wl2_1)
{
    extern __shared__ __align__(16) float psm[];
    float* S00 = psm;                 // 9216
    float* S11 = psm + C * C;         // 9216
    float* V0  = psm + 2 * C * C;     // 96
    float* VB  = V0 + C;              // 96
    float* V1  = VB + C;              // 96

    const int u   = blockIdx.x;
    const int tid = threadIdx.x;

    const float4* s00 = reinterpret_cast<const float4*>(W00 + (size_t)u * C * C);
    const float4* s11 = reinterpret_cast<const float4*>(W11 + (size_t)u * C * C);
    float4* d00 = reinterpret_cast<float4*>(S00);
    float4* d11 = reinterpret_cast<float4*>(S11);
    #pragma unroll
    for (int i = tid; i < C * C / 4; i += PC_NTH) { d00[i] = s00[i]; d11[i] = s11[i]; }
    if (tid < C) { V0[tid] = Wl2_0[tid]; VB[tid] = bl2_0[tid]; V1[tid] = Wl2_1[tid]; }
    __syncthreads();

    if (tid < C) {
        const int w = tid;
        float a = 0.f, b = 0.f, c = 0.f;
        #pragma unroll 8
        for (int v = 0; v < C; v++) {
            float e0 = S00[v * C + w];
            float e1 = S11[v * C + w];
            a = fmaf(V0[v], e0, a);
            b = fmaf(VB[v], e0, b);
            c = fmaf(V1[v], e1, c);
        }
        const float inv_s2 = 1.0f / sqrtf(2.0f * C * C);
        const float inv_s3 = 1.0f / sqrtf(3.0f);
        g_G0[u * C + w] = a * inv_s2;
        g_G1[u * C + w] = b * inv_s2;
        g_G2[u * C + w] = c * inv_s2 * inv_s3;
    }
}

// ---------------------------------------------------------------------------
// Fused main kernel (R13, verified). 256 threads (8 warps, 2/SMSP).
// Mapping: n = lane (node), v0 = warp_id*12 (warp-uniform column slice).
// ---------------------------------------------------------------------------
__global__ void __launch_bounds__(NTH, 1)
main_kernel(const float* __restrict__ nf, const float* __restrict__ pot,
            const float* __restrict__ Wl1_0, const float* __restrict__ Wl1_1,
            const float* __restrict__ Wm1, const float* __restrict__ Wm2,
            const float* __restrict__ Wm3, const float* __restrict__ Wm4,
            const float* __restrict__ Wo0a, const float* __restrict__ Wo0b,
            const float* __restrict__ Wo1a, const float* __restrict__ Wo1b,
            float* __restrict__ out, float silu_cst)
{
    extern __shared__ __align__(16) float sm[];
    float* B   = sm + OFF_B;
    float* B2  = sm + OFF_B2;
    float* X0  = sm + OFF_X0;
    float* X1  = sm + OFF_X1;
    float* Q   = sm + OFF_Q;
    float* F   = sm + OFF_F;
    float* G   = sm + OFF_G;
    float* H1  = sm + OFF_H1;
    float* H2  = sm + OFF_H2;
    float* POT = sm + OFF_POT;

    unsigned smb   = (unsigned)__cvta_generic_to_shared(sm);
    unsigned smbB  = smb + OFF_B  * 4u;
    unsigned smbB2 = smb + OFF_B2 * 4u;
    unsigned smbG  = smb + OFF_G  * 4u;

    const float INVC      = 1.0f / sqrtf((float)C);
    const float INV_SQRT3 = 1.0f / sqrtf(3.0f);
    const float NORM_OUT  = 1.0f / sqrtf(2.0f * C);

    const int tid  = threadIdx.x;
    const int base = blockIdx.x * TILE;
    const int n    = tid & 31;          // lane = node
    const int v0   = (tid >> 5) * 12;   // warp-uniform col slice (8 warps x 12)
    const int row  = base + n;

    // ---- prologue: async B<-Wl1_0, B2<-Wl1_1, G<-nf tile ----
    asyncW(smbB,  Wl1_0);
    asyncW(smbB2, Wl1_1);
    #pragma unroll
    for (int i = 0; i < 12; i++) {
        int idx = tid + i * NTH;
        int r = idx / 96;
        int c = idx - r * 96;
        cpa16(smbG + (unsigned)(r * GS + c * 4) * 4u,
              nf + (size_t)(base + r) * FOURC + c * 4);
    }
    CP_COMMIT();
    if (tid < TILE * 4) POT[(tid >> 2) * PS + (tid & 3)] = pot[base * 4 + tid];
    CP_WAIT0();
    __syncthreads();

    // ---- C1: x0 = nf0 @ Wl1_0 * invC ----
    {
        ull acc[6];
        #pragma unroll
        for (int j = 0; j < 6; j++) acc[j] = 0ULL;
        const float* gn = G + n * GS;
        #pragma unroll 2
        for (int u = 0; u < C; u += 4) {
            float4 a4 = *reinterpret_cast<const float4*>(gn + u);
            ull pv;
            pv = dup2(a4.x); fma2_ns<1>(acc, &pv, B + (u + 0) * C + v0);
            pv = dup2(a4.y); fma2_ns<1>(acc, &pv, B + (u + 1) * C + v0);
            pv = dup2(a4.z); fma2_ns<1>(acc, &pv, B + (u + 2) * C + v0);
            pv = dup2(a4.w); fma2_ns<1>(acc, &pv, B + (u + 3) * C + v0);
        }
        float o[12];
        unp12(o, acc);
        #pragma unroll
        for (int j = 0; j < 12; j++) X0[n * XS + v0 + j] = o[j] * INVC;
    }
    __syncthreads();
    asyncW(smbB, g_G0); CP_COMMIT();   // G0 -> B under C2

    // ---- C2: x1_m = nf1_m @ Wl1_1 * invC (3 streams) ; q ----
    {
        ull acc[18];
        #pragma unroll
        for (int j = 0; j < 18; j++) acc[j] = 0ULL;
        const float* gn = G + n * GS + C;
        #pragma unroll 2
        for (int u = 0; u < C; u += 4) {
            float4 a0 = *reinterpret_cast<const float4*>(gn + u * 3);
            float4 a1 = *reinterpret_cast<const float4*>(gn + u * 3 + 4);
            float4 a2 = *reinterpret_cast<const float4*>(gn + u * 3 + 8);
            ull pv[3];
            pv[0]=dup2(a0.x); pv[1]=dup2(a0.y); pv[2]=dup2(a0.z);
            fma2_ns<3>(acc, pv, B2 + (u + 0) * C + v0);
            pv[0]=dup2(a0.w); pv[1]=dup2(a1.x); pv[2]=dup2(a1.y);
            fma2_ns<3>(acc, pv, B2 + (u + 1) * C + v0);
            pv[0]=dup2(a1.z); pv[1]=dup2(a1.w); pv[2]=dup2(a2.x);
            fma2_ns<3>(acc, pv, B2 + (u + 2) * C + v0);
            pv[0]=dup2(a2.y); pv[1]=dup2(a2.z); pv[2]=dup2(a2.w);
            fma2_ns<3>(acc, pv, B2 + (u + 3) * C + v0);
        }
        float p1 = POT[n*PS+1], p2 = POT[n*PS+2], p3 = POT[n*PS+3];
        float e0[12], e1[12], e2[12];
        unp12(e0, acc); unp12(e1, acc + 6); unp12(e2, acc + 12);
        #pragma unroll
        for (int j = 0; j < 12; j++) {
            float a0 = e0[j]*INVC, a1 = e1[j]*INVC, a2 = e2[j]*INVC;
            X1[0*X1P + n*XS + v0 + j] = a0;
            X1[1*X1P + n*XS + v0 + j] = a1;
            X1[2*X1P + n*XS + v0 + j] = a2;
            Q[n*XS + v0 + j] = a0*p1 + a1*p2 + a2*p3;
        }
    }
    CP_WAIT0(); __syncthreads();
    // prefetch G1 -> B2 and G2 -> G region (nf tile dead) under C3a
    asyncW(smbB2, g_G1);
    asyncW(smbG,  g_G2);
    CP_COMMIT();

    // ---- C3a: s0 = x0@G0 ----
    float s0f[12];
    {
        ull acc[6];
        #pragma unroll
        for (int j = 0; j < 6; j++) acc[j] = 0ULL;
        #pragma unroll 4
        for (int k = 0; k < C; k++) {
            ull pv = dup2(X0[n * XS + k]);
            fma2_ns<1>(acc, &pv, B + k * C + v0);
        }
        unp12(s0f, acc);
    }
    CP_WAIT0(); __syncthreads();
    // prefetch MLP weights into B under fused C3b4
    {
        for (int i = tid; i < 384; i += NTH) cpa16(smbB + (unsigned)i * 16u, Wm1 + i * 4);
        for (int i = tid; i < 64;  i += NTH) cpa16(smbB + (unsigned)(1536 + i * 4) * 4u, Wm2 + i * 4);
        for (int i = tid; i < 64;  i += NTH) cpa16(smbB + (unsigned)(1792 + i * 4) * 4u, Wm3 + i * 4);
        for (int i = tid; i < 1536; i += NTH) cpa16(smbB + (unsigned)(2048 + i * 4) * 4u, Wm4 + i * 4);
        CP_COMMIT();
    }

    // ---- C3b4 (fused): s1 = x0@G1 (B2), s2 = q@G2 (G region) ;
    //      z = p0*s0 + s1 + s2 ; F = z^2 ----
    {
        ull a1[6], a2[6];
        #pragma unroll
        for (int j = 0; j < 6; j++) { a1[j] = 0ULL; a2[j] = 0ULL; }
        #pragma unroll 4
        for (int k = 0; k < C; k++) {
            ull pvx = dup2(X0[n * XS + k]);
            ull pvq = dup2(Q[n * XS + k]);
            fma2_ns<1>(a1, &pvx, B2 + k * C + v0);
            fma2_ns<1>(a2, &pvq, G + k * C + v0);
        }
        float s1f[12], s2f[12];
        unp12(s1f, a1); unp12(s2f, a2);
        float p0 = POT[n*PS];
        #pragma unroll
        for (int j = 0; j < 12; j++) {
            float z = p0 * s0f[j] + s1f[j] + s2f[j];
            F[n * XS + v0 + j] = z * z;
        }
    }
    CP_WAIT0(); __syncthreads();
    asyncW(smbB2, Wo1a); CP_COMMIT();   // under C5 (long)

    // ---- C5: MLP F -> tp_w (G, stride TS) ; MLP weights in B ----
    {
        const float cst = silu_cst;
        #pragma unroll
        for (int idx = tid; idx < TILE * 16; idx += NTH) {
            int nn = idx >> 4, j = idx & 15;
            const float* nr = F + nn * XS;
            float s = 0.f;
            #pragma unroll 8
            for (int u = 0; u < C; u++) s = fmaf(nr[u], B[u * 16 + j], s);
            s *= INVC;
            H1[nn * HS + j] = cst * s / (1.0f + expf(-s));
        }
        __syncthreads();
        #pragma unroll
        for (int idx = tid; idx < TILE * 16; idx += NTH) {
            int nn = idx >> 4, j = idx & 15;
            float s = 0.f;
            #pragma unroll
            for (int k = 0; k < 16; k++) s = fmaf(H1[nn * HS + k], B[1536 + k * 16 + j], s);
            s *= 0.25f;
            H2[nn * HS + j] = cst * s / (1.0f + expf(-s));
        }
        __syncthreads();
        #pragma unroll
        for (int idx = tid; idx < TILE * 16; idx += NTH) {
            int nn = idx >> 4, j = idx & 15;
            float s = 0.f;
            #pragma unroll
            for (int k = 0; k < 16; k++) s = fmaf(H2[nn * HS + k], B[1792 + k * 16 + j], s);
            s *= 0.25f;
            H1[nn * HS + j] = cst * s / (1.0f + expf(-s));
        }
        __syncthreads();
        // tp_w: lane = node, warp cols v0, 4 sections (G2 dead; overwrite region)
        float h[16];
        #pragma unroll
        for (int k = 0; k < 16; k++) h[k] = H1[n * HS + k];
        ull a[24];
        #pragma unroll
        for (int j = 0; j < 24; j++) a[j] = 0ULL;
        #pragma unroll
        for (int k = 0; k < 16; k++) {
            ull pv = dup2(h[k]);
            #pragma unroll
            for (int sec = 0; sec < 4; sec++)
                fma2_ns<1>(a + sec * 6, &pv, B + 2048 + k * FOURC + sec * C + v0);
        }
        __syncthreads();   // all G2 reads (C3b4) complete before overwrite
        #pragma unroll
        for (int sec = 0; sec < 4; sec++) {
            float o[12];
            unp12(o, a + sec * 6);
            float* dst = G + n * TS + sec * C + v0;
            #pragma unroll
            for (int j = 0; j < 12; j++) dst[j] = o[j] * 0.25f;
        }
    }
    CP_WAIT0(); __syncthreads();
    asyncW(smbB, Wo1b); CP_COMMIT();    // under C6

    const float p0 = POT[n*PS];
    const float p1 = POT[n*PS+1], p2 = POT[n*PS+2], p3 = POT[n*PS+3];

    // ---- C6: sa = (w01*x0) @ Wo1a (B2) ----
    float saf[12];
    {
        ull acc[6];
        #pragma unroll
        for (int j = 0; j < 6; j++) acc[j] = 0ULL;
        #pragma unroll 4
        for (int k = 0; k < C; k++) {
            ull pv = dup2(G[n * TS + C + k] * X0[n * XS + k]);
            fma2_ns<1>(acc, &pv, B2 + k * C + v0);
        }
        unp12(saf, acc);
    }
    CP_WAIT0(); __syncthreads();
    asyncW(smbB2, Wo0a); CP_COMMIT();   // under C7

    // ---- C7: sb_m = (w10*x1_m) @ Wo1b (B, 3 streams) ; write out1 ----
    {
        ull acc[18];
        #pragma unroll
        for (int j = 0; j < 18; j++) acc[j] = 0ULL;
        #pragma unroll 2
        for (int k = 0; k < C; k++) {
            float w = G[n * TS + 2 * C + k];
            ull pv[3];
            pv[0] = dup2(w * X1[0*X1P + n*XS + k]);
            pv[1] = dup2(w * X1[1*X1P + n*XS + k]);
            pv[2] = dup2(w * X1[2*X1P + n*XS + k]);
            fma2_ns<3>(acc, pv, B + k * C + v0);
        }
        float e0[12], e1[12], e2[12];
        unp12(e0, acc); unp12(e1, acc + 6); unp12(e2, acc + 12);
        float o[36];
        #pragma unroll
        for (int j = 0; j < 12; j++) {
            float s = saf[j];
            o[j*3+0] = (p1 * s + p0 * e0[j]) * NORM_OUT;
            o[j*3+1] = (p2 * s + p0 * e1[j]) * NORM_OUT;
            o[j*3+2] = (p3 * s + p0 * e2[j]) * NORM_OUT;
        }
        float4* d = reinterpret_cast<float4*>(out + (size_t)row * FOURC + C + v0 * 3);
        #pragma unroll
        for (int i = 0; i < 9; i++) d[i] = reinterpret_cast<const float4*>(o)[i];
    }
    CP_WAIT0(); __syncthreads();
    asyncW(smbB, Wo0b); CP_COMMIT();    // under C8a

    // ---- C8a: o1 = (w00*x0) @ Wo0a (B2) ----
    float o1f[12];
    {
        ull acc[6];
        #pragma unroll
        for (int j = 0; j < 6; j++) acc[j] = 0ULL;
        #pragma unroll 4
        for (int k = 0; k < C; k++) {
            ull pv = dup2(G[n * TS + k] * X0[n * XS + k]);
            fma2_ns<1>(acc, &pv, B2 + k * C + v0);
        }
        unp12(o1f, acc);
    }
    CP_WAIT0(); __syncthreads();

    // ---- C8b: o2 = (w11*q) @ Wo0b (B) ; out0 ----
    {
        ull acc[6];
        #pragma unroll
        for (int j = 0; j < 6; j++) acc[j] = 0ULL;
        #pragma unroll 4
        for (int k = 0; k < C; k++) {
            ull pv = dup2(G[n * TS + 3 * C + k] * Q[n * XS + k]);
            fma2_ns<1>(acc, &pv, B + k * C + v0);
        }
        float o2f[12];
        unp12(o2f, acc);
        float o[12];
        #pragma unroll
        for (int j = 0; j < 12; j++)
            o[j] = (p0 * o1f[j] + o2f[j] * INV_SQRT3) * NORM_OUT;
        float4* d = reinterpret_cast<float4*>(out + (size_t)row * FOURC + v0);
        #pragma unroll
        for (int i = 0; i < 3; i++) d[i] = reinterpret_cast<const float4*>(o)[i];
    }
}

// ---------------------------------------------------------------------------
extern "C" void kernel_launch(void* const* d_in, const int* in_sizes, int n_in,
                              void* d_out, int out_size)
{
    const float* nf    = (const float*)d_in[0];
    const float* pot   = (const float*)d_in[1];
    const float* Wl1_0 = (const float*)d_in[2];
    const float* Wl1_1 = (const float*)d_in[3];
    const float* Wl2_0 = (const float*)d_in[4];
    const float* bl2_0 = (const float*)d_in[5];
    const float* Wl2_1 = (const float*)d_in[6];
    const float* W00   = (const float*)d_in[7];
    const float* W11   = (const float*)d_in[8];
    const float* Wm1   = (const float*)d_in[9];
    const float* Wm2   = (const float*)d_in[10];
    const float* Wm3   = (const float*)d_in[11];
    const float* Wm4   = (const float*)d_in[12];
    const float* Wo0a  = (const float*)d_in[13];
    const float* Wo0b  = (const float*)d_in[14];
    const float* Wo1a  = (const float*)d_in[15];
    const float* Wo1b  = (const float*)d_in[16];
    float* out = (float*)d_out;

    // SILU_CST: input-independent — replicate reference quadrature on host (f64).
    double dz = 24.0 / 200000.0;
    double m2 = 0.0;
    const double inv_sqrt2pi = 0.3989422804014326779399460599343818684759;
    for (int i = 0; i <= 200000; i++) {
        double z = -12.0 + i * dz;
        double s = z / (1.0 + exp(-z));
        m2 += s * s * exp(-0.5 * z * z) * inv_sqrt2pi;
    }
    m2 *= dz;
    float silu_cst = (float)(1.0 / sqrt(m2));

    cudaFuncSetAttribute(precompute_kernel, cudaFuncAttributeMaxDynamicSharedMemorySize, PC_SMEM);
    cudaFuncSetAttribute(main_kernel, cudaFuncAttributeMaxDynamicSharedMemorySize, SMEM_BYTES);

    precompute_kernel<<<C, PC_NTH, PC_SMEM>>>(W00, W11, Wl2_0, bl2_0, Wl2_1);
    main_kernel<<<NCTAS, NTH, SMEM_BYTES>>>(nf, pot, Wl1_0, Wl1_1,
                                            Wm1, Wm2, Wm3, Wm4,
                                            Wo0a, Wo0b, Wo1a, Wo1b, out, silu_cst);
}

// round 17
// speedup vs baseline: 1.2270x; 1.0579x over previous
#include <cuda_runtime.h>
#include <math.h>

#define C 96
#define FOURC 384
#define NN 4096
#define TILE 32
#define NTH 256
#define NCTAS (NN / TILE)   // 128

typedef unsigned long long ull;

#define XS 97               // padded stride for X0/X1/Q/F
#define GS 388              // nf tile rows (16B aligned for cp.async)
#define TS 385              // tp_w rows (odd -> conflict-free scalar)
#define HS 17               // H1/H2 row stride
#define PS 5                // POT row stride
#define X1P (TILE * XS)

// ---------------- shared memory layout (floats) ----------------
#define OFF_B    0          // 9216 : weight buffer A
#define OFF_B2   9216       // 9216 : weight buffer B
#define OFF_X0   18432      // 3104
#define OFF_X1   21536      // 9312
#define OFF_Q    30848      // 3104
#define OFF_F    33952      // 3104
#define OFF_G    37056      // 12416 : nf tile (388), then G2 (96x96), then tp_w (385)
#define OFF_H1   49472      // 544
#define OFF_H2   50016      // 544
#define OFF_POT  50560      // 160
#define OFF_MBAR 50720      // 4 floats (16B) for one mbarrier
#define SMEM_FLOATS 50724
#define SMEM_BYTES (SMEM_FLOATS * 4)   // 202896 B -> 1 CTA/SM, 8 warps

#define WBYTES (C * C * 4)  // 36864

// ---------------- device scratch ----------------
__device__ __align__(16) float g_G0[C * C];
__device__ __align__(16) float g_G1[C * C];
__device__ __align__(16) float g_G2[C * C];

// ---------------- f32x2 helpers ----------------
__device__ __forceinline__ ull dup2(float a) {
    ull r;
    asm("mov.b64 %0, {%1, %1};" : "=l"(r) : "f"(a));
    return r;
}
__device__ __forceinline__ float2 unp2(ull v) {
    float2 r;
    asm("mov.b64 {%0, %1}, %2;" : "=f"(r.x), "=f"(r.y) : "l"(v));
    return r;
}
#define FMA2(d, a, b, cc) asm("fma.rn.f32x2 %0, %1, %2, %3;" : "=l"(d) : "l"(a), "l"(b), "l"(cc))

template<int NS>
__device__ __forceinline__ void fma2_ns(ull* acc, const ull* pv, const float* wrow)
{
    ulonglong2 wa = *reinterpret_cast<const ulonglong2*>(wrow);
    ulonglong2 wb = *reinterpret_cast<const ulonglong2*>(wrow + 4);
    ulonglong2 wc = *reinterpret_cast<const ulonglong2*>(wrow + 8);
    ull w0 = wa.x, w1 = wa.y, w2 = wb.x, w3 = wb.y, w4 = wc.x, w5 = wc.y;
    #pragma unroll
    for (int s = 0; s < NS; s++) {
        FMA2(acc[s*6+0], pv[s], w0, acc[s*6+0]);
        FMA2(acc[s*6+1], pv[s], w1, acc[s*6+1]);
        FMA2(acc[s*6+2], pv[s], w2, acc[s*6+2]);
        FMA2(acc[s*6+3], pv[s], w3, acc[s*6+3]);
        FMA2(acc[s*6+4], pv[s], w4, acc[s*6+4]);
        FMA2(acc[s*6+5], pv[s], w5, acc[s*6+5]);
    }
}

__device__ __forceinline__ void unp12(float o[12], const ull a[6])
{
    #pragma unroll
    for (int j = 0; j < 6; j++) {
        float2 p = unp2(a[j]);
        o[2*j] = p.x; o[2*j+1] = p.y;
    }
}

// ---------------- cp.async (nf tile only) ----------------
__device__ __forceinline__ void cpa16(unsigned dst, const float* src) {
    asm volatile("cp.async.ca.shared.global [%0], [%1], 16;" :: "r"(dst), "l"(src) : "memory");
}
#define CP_COMMIT() asm volatile("cp.async.commit_group;" ::: "memory")
#define CP_WAIT0()  asm volatile("cp.async.wait_group 0;" ::: "memory")

// ---------------- TMA bulk copy + mbarrier ----------------
__device__ __forceinline__ void mbar_init1(unsigned mbar) {
    asm volatile("mbarrier.init.shared.b64 [%0], 1;" :: "r"(mbar) : "memory");
}
__device__ __forceinline__ void mbar_expect(unsigned mbar, unsigned bytes) {
    asm volatile("mbarrier.arrive.expect_tx.shared.b64 _, [%0], %1;"
                 :: "r"(mbar), "r"(bytes) : "memory");
}
__device__ __forceinline__ void bulkcp(unsigned dst, const float* src, unsigned bytes, unsigned mbar) {
    asm volatile("cp.async.bulk.shared::cta.global.mbarrier::complete_tx::bytes "
                 "[%0], [%1], %2, [%3];"
                 :: "r"(dst), "l"(src), "r"(bytes), "r"(mbar) : "memory");
}
__device__ __forceinline__ void mbar_wait(unsigned mbar, unsigned parity) {
    asm volatile(
        "{\n\t"
        ".reg .pred P;\n\t"
        "WAIT_%=:\n\t"
        "mbarrier.try_wait.parity.acquire.cta.shared::cta.b64 P, [%0], %1, 0x989680;\n\t"
        "@P bra DONE_%=;\n\t"
        "bra WAIT_%=;\n\t"
        "DONE_%=:\n\t"
        "}"
        :: "r"(mbar), "r"(parity) : "memory");
}

// ---------------------------------------------------------------------------
// Precompute (fast): one CTA per u.
// ---------------------------------------------------------------------------
#define PC_NTH 256
#define PC_SMEM ((2 * C * C + 3 * C) * 4)   // 74880 B
__global__ void __launch_bounds__(PC_NTH)
precompute_kernel(const float* __restrict__ W00,
                  const float* __restrict__ W11,
                  const float* __restrict__ Wl2_0,
                  const float* __restrict__ bl2_0,
                  const float* __restrict__ Wl2_1)
{
    extern __shared__ __align__(16) float psm[];
    float* S00 = psm;
    float* S11 = psm + C * C;
    float* V0  = psm + 2 * C * C;
    float* VB  = V0 + C;
    float* V1  = VB + C;

    const int u   = blockIdx.x;
    const int tid = threadIdx.x;

    const float4* s00 = reinterpret_cast<const float4*>(W00 + (size_t)u * C * C);
    const float4* s11 = reinterpret_cast<const float4*>(W11 + (size_t)u * C * C);
    float4* d00 = reinterpret_cast<float4*>(S00);
    float4* d11 = reinterpret_cast<float4*>(S11);
    #pragma unroll
    for (int i = tid; i < C * C / 4; i += PC_NTH) { d00[i] = s00[i]; d11[i] = s11[i]; }
    if (tid < C) { V0[tid] = Wl2_0[tid]; VB[tid] = bl2_0[tid]; V1[tid] = Wl2_1[tid]; }
    __syncthreads();

    if (tid < C) {
        const int w = tid;
        float a = 0.f, b = 0.f, c = 0.f;
        #pragma unroll 8
        for (int v = 0; v < C; v++) {
            float e0 = S00[v * C + w];
            float e1 = S11[v * C + w];
            a = fmaf(V0[v], e0, a);
            b = fmaf(VB[v], e0, b);
            c = fmaf(V1[v], e1, c);
        }
        const float inv_s2 = 1.0f / sqrtf(2.0f * C * C);
        const float inv_s3 = 1.0f / sqrtf(3.0f);
        g_G0[u * C + w] = a * inv_s2;
        g_G1[u * C + w] = b * inv_s2;
        g_G2[u * C + w] = c * inv_s2 * inv_s3;
    }
}

// ---------------------------------------------------------------------------
// Fused main kernel: R16 schedule with TMA-bulk weight staging (8 phases).
// Mapping: n = lane (node), v0 = warp_id*12.
// ---------------------------------------------------------------------------
__global__ void __launch_bounds__(NTH, 1)
main_kernel(const float* __restrict__ nf, const float* __restrict__ pot,
            const float* __restrict__ Wl1_0, const float* __restrict__ Wl1_1,
            const float* __restrict__ Wm1, const float* __restrict__ Wm2,
            const float* __restrict__ Wm3, const float* __restrict__ Wm4,
            const float* __restrict__ Wo0a, const float* __restrict__ Wo0b,
            const float* __restrict__ Wo1a, const float* __restrict__ Wo1b,
            float* __restrict__ out, float silu_cst)
{
    extern __shared__ __align__(16) float sm[];
    float* B   = sm + OFF_B;
    float* B2  = sm + OFF_B2;
    float* X0  = sm + OFF_X0;
    float* X1  = sm + OFF_X1;
    float* Q   = sm + OFF_Q;
    float* F   = sm + OFF_F;
    float* G   = sm + OFF_G;
    float* H1  = sm + OFF_H1;
    float* H2  = sm + OFF_H2;
    float* POT = sm + OFF_POT;

    unsigned smb   = (unsigned)__cvta_generic_to_shared(sm);
    unsigned smbB  = smb + OFF_B    * 4u;
    unsigned smbB2 = smb + OFF_B2   * 4u;
    unsigned smbG  = smb + OFF_G    * 4u;
    unsigned mb    = smb + OFF_MBAR * 4u;

    const float INVC      = 1.0f / sqrtf((float)C);
    const float INV_SQRT3 = 1.0f / sqrtf(3.0f);
    const float NORM_OUT  = 1.0f / sqrtf(2.0f * C);

    const int tid  = threadIdx.x;
    const int base = blockIdx.x * TILE;
    const int n    = tid & 31;          // lane = node
    const int v0   = (tid >> 5) * 12;   // warp-uniform col slice
    const int row  = base + n;

    // ---- prologue ----
    if (tid == 0) mbar_init1(mb);
    __syncthreads();                    // init visible before any wait
    if (tid == 0) {                     // S1: Wl1_0 -> B, Wl1_1 -> B2
        mbar_expect(mb, 2 * WBYTES);
        bulkcp(smbB,  Wl1_0, WBYTES, mb);
        bulkcp(smbB2, Wl1_1, WBYTES, mb);
    }
    #pragma unroll
    for (int i = 0; i < 12; i++) {      // nf tile via LDGSTS (padded stride)
        int idx = tid + i * NTH;
        int r = idx / 96;
        int c = idx - r * 96;
        cpa16(smbG + (unsigned)(r * GS + c * 4) * 4u,
              nf + (size_t)(base + r) * FOURC + c * 4);
    }
    CP_COMMIT();
    if (tid < TILE * 4) POT[(tid >> 2) * PS + (tid & 3)] = pot[base * 4 + tid];
    CP_WAIT0();
    mbar_wait(mb, 0);                   // S1 done
    __syncthreads();

    // ---- C1: x0 = nf0 @ Wl1_0 * invC ----
    {
        ull acc[6];
        #pragma unroll
        for (int j = 0; j < 6; j++) acc[j] = 0ULL;
        const float* gn = G + n * GS;
        #pragma unroll 2
        for (int u = 0; u < C; u += 4) {
            float4 a4 = *reinterpret_cast<const float4*>(gn + u);
            ull pv;
            pv = dup2(a4.x); fma2_ns<1>(acc, &pv, B + (u + 0) * C + v0);
            pv = dup2(a4.y); fma2_ns<1>(acc, &pv, B + (u + 1) * C + v0);
            pv = dup2(a4.z); fma2_ns<1>(acc, &pv, B + (u + 2) * C + v0);
            pv = dup2(a4.w); fma2_ns<1>(acc, &pv, B + (u + 3) * C + v0);
        }
        float o[12];
        unp12(o, acc);
        #pragma unroll
        for (int j = 0; j < 12; j++) X0[n * XS + v0 + j] = o[j] * INVC;
    }
    __syncthreads();                    // B free
    if (tid == 0) {                     // S2: G0 -> B (under C2)
        mbar_expect(mb, WBYTES);
        bulkcp(smbB, g_G0, WBYTES, mb);
    }

    // ---- C2: x1_m = nf1_m @ Wl1_1 * invC (3 streams) ; q ----
    {
        ull acc[18];
        #pragma unroll
        for (int j = 0; j < 18; j++) acc[j] = 0ULL;
        const float* gn = G + n * GS + C;
        #pragma unroll 2
        for (int u = 0; u < C; u += 4) {
            float4 a0 = *reinterpret_cast<const float4*>(gn + u * 3);
            float4 a1 = *reinterpret_cast<const float4*>(gn + u * 3 + 4);
            float4 a2 = *reinterpret_cast<const float4*>(gn + u * 3 + 8);
            ull pv[3];
            pv[0]=dup2(a0.x); pv[1]=dup2(a0.y); pv[2]=dup2(a0.z);
            fma2_ns<3>(acc, pv, B2 + (u + 0) * C + v0);
            pv[0]=dup2(a0.w); pv[1]=dup2(a1.x); pv[2]=dup2(a1.y);
            fma2_ns<3>(acc, pv, B2 + (u + 1) * C + v0);
            pv[0]=dup2(a1.z); pv[1]=dup2(a1.w); pv[2]=dup2(a2.x);
            fma2_ns<3>(acc, pv, B2 + (u + 2) * C + v0);
            pv[0]=dup2(a2.y); pv[1]=dup2(a2.z); pv[2]=dup2(a2.w);
            fma2_ns<3>(acc, pv, B2 + (u + 3) * C + v0);
        }
        float p1 = POT[n*PS+1], p2 = POT[n*PS+2], p3 = POT[n*PS+3];
        float e0[12], e1[12], e2[12];
        unp12(e0, acc); unp12(e1, acc + 6); unp12(e2, acc + 12);
        #pragma unroll
        for (int j = 0; j < 12; j++) {
            float a0 = e0[j]*INVC, a1 = e1[j]*INVC, a2 = e2[j]*INVC;
            X1[0*X1P + n*XS + v0 + j] = a0;
            X1[1*X1P + n*XS + v0 + j] = a1;
            X1[2*X1P + n*XS + v0 + j] = a2;
            Q[n*XS + v0 + j] = a0*p1 + a1*p2 + a2*p3;
        }
    }
    mbar_wait(mb, 1); __syncthreads();  // S2 done; B2/nf free
    if (tid == 0) {                     // S3: G1 -> B2, G2 -> G (under C3a)
        mbar_expect(mb, 2 * WBYTES);
        bulkcp(smbB2, g_G1, WBYTES, mb);
        bulkcp(smbG,  g_G2, WBYTES, mb);
    }

    // ---- C3a: s0 = x0@G0 ----
    float s0f[12];
    {
        ull acc[6];
        #pragma unroll
        for (int j = 0; j < 6; j++) acc[j] = 0ULL;
        #pragma unroll 4
        for (int k = 0; k < C; k++) {
            ull pv = dup2(X0[n * XS + k]);
            fma2_ns<1>(acc, &pv, B + k * C + v0);
        }
        unp12(s0f, acc);
    }
    mbar_wait(mb, 0); __syncthreads();  // S3 done; B free
    if (tid == 0) {                     // S4: MLP weights -> B (under C3b4)
        mbar_expect(mb, 32768);
        bulkcp(smbB,                Wm1, 6144,  mb);
        bulkcp(smbB + 1536u * 4u,   Wm2, 1024,  mb);
        bulkcp(smbB + 1792u * 4u,   Wm3, 1024,  mb);
        bulkcp(smbB + 2048u * 4u,   Wm4, 24576, mb);
    }

    // ---- C3b4 (fused): s1 = x0@G1 (B2), s2 = q@G2 (G) ; F = (p0*s0+s1+s2)^2 ----
    {
        ull a1[6], a2[6];
        #pragma unroll
        for (int j = 0; j < 6; j++) { a1[j] = 0ULL; a2[j] = 0ULL; }
        #pragma unroll 4
        for (int k = 0; k < C; k++) {
            ull pvx = dup2(X0[n * XS + k]);
            ull pvq = dup2(Q[n * XS + k]);
            fma2_ns<1>(a1, &pvx, B2 + k * C + v0);
            fma2_ns<1>(a2, &pvq, G + k * C + v0);
        }
        float s1f[12], s2f[12];
        unp12(s1f, a1); unp12(s2f, a2);
        float p0 = POT[n*PS];
        #pragma unroll
        for (int j = 0; j < 12; j++) {
            float z = p0 * s0f[j] + s1f[j] + s2f[j];
            F[n * XS + v0 + j] = z * z;
        }
    }
    mbar_wait(mb, 1); __syncthreads();  // S4 done; B2 free
    if (tid == 0) {                     // S5: Wo1a -> B2 (under C5)
        mbar_expect(mb, WBYTES);
        bulkcp(smbB2, Wo1a, WBYTES, mb);
    }

    // ---- C5: MLP F -> tp_w (G, stride TS) ; MLP weights in B ----
    {
        const float cst = silu_cst;
        #pragma unroll
        for (int idx = tid; idx < TILE * 16; idx += NTH) {
            int nn = idx >> 4, j = idx & 15;
            const float* nr = F + nn * XS;
            float s = 0.f;
            #pragma unroll 8
            for (int u = 0; u < C; u++) s = fmaf(nr[u], B[u * 16 + j], s);
            s *= INVC;
            H1[nn * HS + j] = cst * s / (1.0f + expf(-s));
        }
        __syncthreads();
        #pragma unroll
        for (int idx = tid; idx < TILE * 16; idx += NTH) {
            int nn = idx >> 4, j = idx & 15;
            float s = 0.f;
            #pragma unroll
            for (int k = 0; k < 16; k++) s = fmaf(H1[nn * HS + k], B[1536 + k * 16 + j], s);
            s *= 0.25f;
            H2[nn * HS + j] = cst * s / (1.0f + expf(-s));
        }
        __syncthreads();
        #pragma unroll
        for (int idx = tid; idx < TILE * 16; idx += NTH) {
            int nn = idx >> 4, j = idx & 15;
            float s = 0.f;
            #pragma unroll
            for (int k = 0; k < 16; k++) s = fmaf(H2[nn * HS + k], B[1792 + k * 16 + j], s);
            s *= 0.25f;
            H1[nn * HS + j] = cst * s / (1.0f + expf(-s));
        }
        __syncthreads();
        float h[16];
        #pragma unroll
        for (int k = 0; k < 16; k++) h[k] = H1[n * HS + k];
        ull a[24];
        #pragma unroll
        for (int j = 0; j < 24; j++) a[j] = 0ULL;
        #pragma unroll
        for (int k = 0; k < 16; k++) {
            ull pv = dup2(h[k]);
            #pragma unroll
            for (int sec = 0; sec < 4; sec++)
                fma2_ns<1>(a + sec * 6, &pv, B + 2048 + k * FOURC + sec * C + v0);
        }
        __syncthreads();   // all G2 reads (C3b4) complete before overwrite
        #pragma unroll
        for (int sec = 0; sec < 4; sec++) {
            float o[12];
            unp12(o, a + sec * 6);
            float* dst = G + n * TS + sec * C + v0;
            #pragma unroll
            for (int j = 0; j < 12; j++) dst[j] = o[j] * 0.25f;
        }
    }
    mbar_wait(mb, 0); __syncthreads();  // S5 done; B free
    if (tid == 0) {                     // S6: Wo1b -> B (under C6)
        mbar_expect(mb, WBYTES);
        bulkcp(smbB, Wo1b, WBYTES, mb);
    }

    const float p0 = POT[n*PS];
    const float p1 = POT[n*PS+1], p2 = POT[n*PS+2], p3 = POT[n*PS+3];

    // ---- C6: sa = (w01*x0) @ Wo1a (B2) ----
    float saf[12];
    {
        ull acc[6];
        #pragma unroll
        for (int j = 0; j < 6; j++) acc[j] = 0ULL;
        #pragma unroll 4
        for (int k = 0; k < C; k++) {
            ull pv = dup2(G[n * TS + C + k] * X0[n * XS + k]);
            fma2_ns<1>(acc, &pv, B2 + k * C + v0);
        }
        unp12(saf, acc);
    }
    mbar_wait(mb, 1); __syncthreads();  // S6 done; B2 free
    if (tid == 0) {                     // S7: Wo0a -> B2 (under C7)
        mbar_expect(mb, WBYTES);
        bulkcp(smbB2, Wo0a, WBYTES, mb);
    }

    // ---- C7: sb_m = (w10*x1_m) @ Wo1b (B, 3 streams) ; write out1 ----
    {
        ull acc[18];
        #pragma unroll
        for (int j = 0; j < 18; j++) acc[j] = 0ULL;
        #pragma unroll 2
        for (int k = 0; k < C; k++) {
            float w = G[n * TS + 2 * C + k];
            ull pv[3];
            pv[0] = dup2(w * X1[0*X1P + n*XS + k]);
            pv[1] = dup2(w * X1[1*X1P + n*XS + k]);
            pv[2] = dup2(w * X1[2*X1P + n*XS + k]);
            fma2_ns<3>(acc, pv, B + k * C + v0);
        }
        float e0[12], e1[12], e2[12];
        unp12(e0, acc); unp12(e1, acc + 6); unp12(e2, acc + 12);
        float o[36];
        #pragma unroll
        for (int j = 0; j < 12; j++) {
            float s = saf[j];
            o[j*3+0] = (p1 * s + p0 * e0[j]) * NORM_OUT;
            o[j*3+1] = (p2 * s + p0 * e1[j]) * NORM_OUT;
            o[j*3+2] = (p3 * s + p0 * e2[j]) * NORM_OUT;
        }
        float4* d = reinterpret_cast<float4*>(out + (size_t)row * FOURC + C + v0 * 3);
        #pragma unroll
        for (int i = 0; i < 9; i++) d[i] = reinterpret_cast<const float4*>(o)[i];
    }
    mbar_wait(mb, 0); __syncthreads();  // S7 done; B free
    if (tid == 0) {                     // S8: Wo0b -> B (under C8a)
        mbar_expect(mb, WBYTES);
        bulkcp(smbB, Wo0b, WBYTES, mb);
    }

    // ---- C8a: o1 = (w00*x0) @ Wo0a (B2) ----
    float o1f[12];
    {
        ull acc[6];
        #pragma unroll
        for (int j = 0; j < 6; j++) acc[j] = 0ULL;
        #pragma unroll 4
        for (int k = 0; k < C; k++) {
            ull pv = dup2(G[n * TS + k] * X0[n * XS + k]);
            fma2_ns<1>(acc, &pv, B2 + k * C + v0);
        }
        unp12(o1f, acc);
    }
    mbar_wait(mb, 1); __syncthreads();  // S8 done

    // ---- C8b: o2 = (w11*q) @ Wo0b (B) ; out0 ----
    {
        ull acc[6];
        #pragma unroll
        for (int j = 0; j < 6; j++) acc[j] = 0ULL;
        #pragma unroll 4
        for (int k = 0; k < C; k++) {
            ull pv = dup2(G[n * TS + 3 * C + k] * Q[n * XS + k]);
            fma2_ns<1>(acc, &pv, B + k * C + v0);
        }
        float o2f[12];
        unp12(o2f, acc);
        float o[12];
        #pragma unroll
        for (int j = 0; j < 12; j++)
            o[j] = (p0 * o1f[j] + o2f[j] * INV_SQRT3) * NORM_OUT;
        float4* d = reinterpret_cast<float4*>(out + (size_t)row * FOURC + v0);
        #pragma unroll
        for (int i = 0; i < 3; i++) d[i] = reinterpret_cast<const float4*>(o)[i];
    }
}

// ---------------------------------------------------------------------------
extern "C" void kernel_launch(void* const* d_in, const int* in_sizes, int n_in,
                              void* d_out, int out_size)
{
    const float* nf    = (const float*)d_in[0];
    const float* pot   = (const float*)d_in[1];
    const float* Wl1_0 = (const float*)d_in[2];
    const float* Wl1_1 = (const float*)d_in[3];
    const float* Wl2_0 = (const float*)d_in[4];
    const float* bl2_0 = (const float*)d_in[5];
    const float* Wl2_1 = (const float*)d_in[6];
    const float* W00   = (const float*)d_in[7];
    const float* W11   = (const float*)d_in[8];
    const float* Wm1   = (const float*)d_in[9];
    const float* Wm2   = (const float*)d_in[10];
    const float* Wm3   = (const float*)d_in[11];
    const float* Wm4   = (const float*)d_in[12];
    const float* Wo0a  = (const float*)d_in[13];
    const float* Wo0b  = (const float*)d_in[14];
    const float* Wo1a  = (const float*)d_in[15];
    const float* Wo1b  = (const float*)d_in[16];
    float* out = (float*)d_out;

    // SILU_CST: input-independent — replicate reference quadrature on host (f64).
    double dz = 24.0 / 200000.0;
    double m2 = 0.0;
    const double inv_sqrt2pi = 0.3989422804014326779399460599343818684759;
    for (int i = 0; i <= 200000; i++) {
        double z = -12.0 + i * dz;
        double s = z / (1.0 + exp(-z));
        m2 += s * s * exp(-0.5 * z * z) * inv_sqrt2pi;
    }
    m2 *= dz;
    float silu_cst = (float)(1.0 / sqrt(m2));

    cudaFuncSetAttribute(precompute_kernel, cudaFuncAttributeMaxDynamicSharedMemorySize, PC_SMEM);
    cudaFuncSetAttribute(main_kernel, cudaFuncAttributeMaxDynamicSharedMemorySize, SMEM_BYTES);

    precompute_kernel<<<C, PC_NTH, PC_SMEM>>>(W00, W11, Wl2_0, bl2_0, Wl2_1);
    main_kernel<<<NCTAS, NTH, SMEM_BYTES>>>(nf, pot, Wl1_0, Wl1_1,
                                            Wm1, Wm2, Wm3, Wm4,
                                            Wo0a, Wo0b, Wo1a, Wo1b, out, silu_cst);
}